// round 5
// baseline (speedup 1.0000x reference)
#include <cuda_runtime.h>
#include <math.h>

// Problem constants
#define BB     128      // batch
#define TT     512      // timesteps
#define FF     256      // input features
#define HH     1024     // hidden (ghost + intr)
#define GST    512      // ghost size
#define ITR    512      // intr size
#define KGC    1280     // F + H (gate / candidate K)

// Launch shape
#define NCTAS  128
#define NTHR   256
#define RG     8        // gate rows per CTA   (1024 / 128)
#define RC     4        // cand rows per CTA   (512 / 128)
#define RH     4        // ghost rows per CTA  (512 / 128)

// ---------------- device globals (scratch + barrier state) ----------------
__device__ unsigned g_bar_count = 0;                 // wraps to 0 every barrier
__device__ unsigned g_bar_sense = 0;                 // even #barriers -> ends at 0
__device__ __align__(16) float g_rstate[BB * ITR];   // r * h_intr
__device__ __align__(16) float g_uq[BB * ITR];       // u gate values

// Grid-wide sense-reversing barrier. Requires all NCTAS CTAs co-resident:
// 128 CTAs <= 148 SMs at 1 CTA/SM -> single wave, guaranteed.
__device__ __forceinline__ void grid_barrier(unsigned sense) {
    __syncthreads();
    if (threadIdx.x == 0) {
        __threadfence();                                   // publish writes to L2
        unsigned old = atomicInc(&g_bar_count, NCTAS - 1u);
        if (old == NCTAS - 1u) {
            atomicExch(&g_bar_sense, sense);               // release all
        } else {
            while (((volatile unsigned*)&g_bar_sense)[0] != sense) { }
        }
        __threadfence();
    }
    __syncthreads();
}

__device__ __forceinline__ void fma4(float& acc, float4 w, float4 s) {
    acc = fmaf(w.x, s.x, acc);
    acc = fmaf(w.y, s.y, acc);
    acc = fmaf(w.z, s.z, acc);
    acc = fmaf(w.w, s.w, acc);
}

// Multi-value butterfly reduction: 32 lane-distributed partial sums
// -> lane L ends holding the full (cross-lane) total of v[L]. 31 SHFLs.
__device__ __forceinline__ float red32(float* v, int lane) {
    #pragma unroll
    for (int i = 0; i < 16; ++i) {
        float a = v[i]      + __shfl_xor_sync(0xffffffffu, v[i],      16);
        float b = v[i + 16] + __shfl_xor_sync(0xffffffffu, v[i + 16], 16);
        v[i] = (lane & 16) ? b : a;
    }
    #pragma unroll
    for (int i = 0; i < 8; ++i) {
        float a = v[i]     + __shfl_xor_sync(0xffffffffu, v[i],     8);
        float b = v[i + 8] + __shfl_xor_sync(0xffffffffu, v[i + 8], 8);
        v[i] = (lane & 8) ? b : a;
    }
    #pragma unroll
    for (int i = 0; i < 4; ++i) {
        float a = v[i]     + __shfl_xor_sync(0xffffffffu, v[i],     4);
        float b = v[i + 4] + __shfl_xor_sync(0xffffffffu, v[i + 4], 4);
        v[i] = (lane & 4) ? b : a;
    }
    #pragma unroll
    for (int i = 0; i < 2; ++i) {
        float a = v[i]     + __shfl_xor_sync(0xffffffffu, v[i],     2);
        float b = v[i + 2] + __shfl_xor_sync(0xffffffffu, v[i + 2], 2);
        v[i] = (lane & 2) ? b : a;
    }
    {
        float a = v[0] + __shfl_xor_sync(0xffffffffu, v[0], 1);
        float b = v[1] + __shfl_xor_sync(0xffffffffu, v[1], 1);
        v[0] = (lane & 1) ? b : a;
    }
    return v[0];
}

// h(t-1) row for batch b: hidden input at t=0, else previous output row.
__device__ __forceinline__ const float* hrow(const float* hid, const float* out,
                                             int t, int b) {
    return (t == 0) ? (hid + (size_t)b * HH)
                    : (out + ((size_t)b * TT + (size_t)(t - 1)) * HH);
}

extern "C" __global__ void __launch_bounds__(NTHR, 1)
ghostgru_persistent(const float* __restrict__ x,     // (B, T, F)
                    const float* __restrict__ hid,   // (B, 1, H)
                    const float* __restrict__ Wg,    // (1024, 1280)
                    const float* __restrict__ Wc,    // (512, 1280)
                    const float* __restrict__ Wh,    // (512, 512)
                    const float* __restrict__ bg,    // (1024,)
                    const float* __restrict__ bc,    // (512,)
                    const float* __restrict__ bh,    // (512,)
                    float*       __restrict__ out,   // (B,T,H) [+ (B,H) tail]
                    int out_size)
{
    extern __shared__ float sm[];
    float* sWg = sm;                    // RG*KGC = 10240 floats
    float* sWc = sWg + RG * KGC;        // RC*KGC = 5120
    float* sWh = sWc + RC * KGC;        // RH*ITR = 2048
    float* sBg = sWh + RH * ITR;        // RG
    float* sBc = sBg + RG;              // RC
    float* sBh = sBc + RC;              // RH

    const int cta  = blockIdx.x;
    const int tid  = threadIdx.x;
    const int wrp  = tid >> 5;
    const int lane = tid & 31;

    // ---- stage this CTA's weight slices into SMEM (weight-stationary) ----
    {
        const float4* s1 = (const float4*)(Wg + (size_t)cta * (RG * KGC));
        float4* d1 = (float4*)sWg;
        for (int i = tid; i < RG * KGC / 4; i += NTHR) d1[i] = s1[i];
        const float4* s2 = (const float4*)(Wc + (size_t)cta * (RC * KGC));
        float4* d2 = (float4*)sWc;
        for (int i = tid; i < RC * KGC / 4; i += NTHR) d2[i] = s2[i];
        const float4* s3 = (const float4*)(Wh + (size_t)cta * (RH * ITR));
        float4* d3 = (float4*)sWh;
        for (int i = tid; i < RH * ITR / 4; i += NTHR) d3[i] = s3[i];
        if (tid < RG) sBg[tid] = bg[cta * RG + tid];
        if (tid < RC) sBc[tid] = bc[cta * RC + tid];
        if (tid < RH) sBh[tid] = bh[cta * RH + tid];
    }
    __syncthreads();

    const float4* sWg4 = (const float4*)sWg;   // row stride 320 float4
    const float4* sWc4 = (const float4*)sWc;   // row stride 320 float4
    const float4* sWh4 = (const float4*)sWh;   // row stride 128 float4

    const int  ng0  = cta * RG;                // first gate neuron owned
    const int  nc0  = cta * RC;                // first cand / intr neuron owned
    const int  nh0  = cta * RH;                // first ghost neuron owned
    const bool is_r = (ng0 < ITR);             // CTAs 0..63: r rows; 64..127: u rows

    unsigned sense = 0;

    for (int t = 0; t < TT; ++t) {
        // ============ phase 1: gate = sigmoid([x_t, h] @ Wg^T + bg) ============
        // warp handles 4 batches per group, 4 groups; 8 neurons x 4 batches accs.
        for (int g = 0; g < 4; ++g) {
            const int b0 = g * 32 + wrp * 4;
            const float4* xr0 = (const float4*)(x + ((size_t)(b0 + 0) * TT + t) * FF);
            const float4* xr1 = (const float4*)(x + ((size_t)(b0 + 1) * TT + t) * FF);
            const float4* xr2 = (const float4*)(x + ((size_t)(b0 + 2) * TT + t) * FF);
            const float4* xr3 = (const float4*)(x + ((size_t)(b0 + 3) * TT + t) * FF);
            const float4* hr0 = (const float4*)hrow(hid, out, t, b0 + 0);
            const float4* hr1 = (const float4*)hrow(hid, out, t, b0 + 1);
            const float4* hr2 = (const float4*)hrow(hid, out, t, b0 + 2);
            const float4* hr3 = (const float4*)hrow(hid, out, t, b0 + 3);

            float acc[32];
            #pragma unroll
            for (int i = 0; i < 32; ++i) acc[i] = 0.f;

            #pragma unroll
            for (int kc = 0; kc < 2; ++kc) {           // x segment: 64 float4
                const int k4 = kc * 32 + lane;
                float4 s0 = __ldg(xr0 + k4);
                float4 s1 = __ldg(xr1 + k4);
                float4 s2 = __ldg(xr2 + k4);
                float4 s3 = __ldg(xr3 + k4);
                #pragma unroll
                for (int j = 0; j < RG; ++j) {
                    float4 wv = sWg4[j * 320 + k4];
                    fma4(acc[j * 4 + 0], wv, s0);
                    fma4(acc[j * 4 + 1], wv, s1);
                    fma4(acc[j * 4 + 2], wv, s2);
                    fma4(acc[j * 4 + 3], wv, s3);
                }
            }
            #pragma unroll
            for (int kc = 0; kc < 8; ++kc) {           // h segment: 256 float4
                const int k4 = kc * 32 + lane;
                float4 s0 = __ldcg(hr0 + k4);
                float4 s1 = __ldcg(hr1 + k4);
                float4 s2 = __ldcg(hr2 + k4);
                float4 s3 = __ldcg(hr3 + k4);
                #pragma unroll
                for (int j = 0; j < RG; ++j) {
                    float4 wv = sWg4[j * 320 + 64 + k4];
                    fma4(acc[j * 4 + 0], wv, s0);
                    fma4(acc[j * 4 + 1], wv, s1);
                    fma4(acc[j * 4 + 2], wv, s2);
                    fma4(acc[j * 4 + 3], wv, s3);
                }
            }

            float tot = red32(acc, lane);     // lane L holds (j = L>>2, bi = L&3)
            const int j  = lane >> 2;
            const int bi = lane & 3;
            const int b  = b0 + bi;
            const int n  = ng0 + j;
            float z = tot + sBg[j];
            float gval = 1.0f / (1.0f + __expf(-z));
            if (is_r) {
                float hi = __ldcg(hrow(hid, out, t, b) + GST + n);
                g_rstate[(size_t)b * ITR + n] = gval * hi;
            } else {
                g_uq[(size_t)b * ITR + (n - GST)] = gval;
            }
        }
        sense ^= 1u; grid_barrier(sense);

        // ====== phase 2: c = tanh([x, h_ghost, r_state] @ Wc^T + bc); new_h ======
        // warp handles 8 batches per group, 2 groups; 4 neurons x 8 batches accs.
        for (int g = 0; g < 2; ++g) {
            const int b0 = g * 64 + wrp * 8;
            const float4* xp[8]; const float4* gp[8]; const float4* rp[8];
            #pragma unroll
            for (int bi = 0; bi < 8; ++bi) {
                const int b = b0 + bi;
                xp[bi] = (const float4*)(x + ((size_t)b * TT + t) * FF);
                gp[bi] = (const float4*)hrow(hid, out, t, b);          // h[0:512)
                rp[bi] = (const float4*)(g_rstate + (size_t)b * ITR);
            }

            float acc[32];
            #pragma unroll
            for (int i = 0; i < 32; ++i) acc[i] = 0.f;

            #pragma unroll
            for (int kc = 0; kc < 2; ++kc) {           // x: 64 float4
                const int k4 = kc * 32 + lane;
                float4 sv[8];
                #pragma unroll
                for (int bi = 0; bi < 8; ++bi) sv[bi] = __ldg(xp[bi] + k4);
                #pragma unroll
                for (int j = 0; j < RC; ++j) {
                    float4 wv = sWc4[j * 320 + k4];
                    #pragma unroll
                    for (int bi = 0; bi < 8; ++bi) fma4(acc[j * 8 + bi], wv, sv[bi]);
                }
            }
            #pragma unroll
            for (int kc = 0; kc < 4; ++kc) {           // h ghost part: 128 float4
                const int k4 = kc * 32 + lane;
                float4 sv[8];
                #pragma unroll
                for (int bi = 0; bi < 8; ++bi) sv[bi] = __ldcg(gp[bi] + k4);
                #pragma unroll
                for (int j = 0; j < RC; ++j) {
                    float4 wv = sWc4[j * 320 + 64 + k4];
                    #pragma unroll
                    for (int bi = 0; bi < 8; ++bi) fma4(acc[j * 8 + bi], wv, sv[bi]);
                }
            }
            #pragma unroll
            for (int kc = 0; kc < 4; ++kc) {           // r_state: 128 float4
                const int k4 = kc * 32 + lane;
                float4 sv[8];
                #pragma unroll
                for (int bi = 0; bi < 8; ++bi) sv[bi] = __ldcg(rp[bi] + k4);
                #pragma unroll
                for (int j = 0; j < RC; ++j) {
                    float4 wv = sWc4[j * 320 + 192 + k4];
                    #pragma unroll
                    for (int bi = 0; bi < 8; ++bi) fma4(acc[j * 8 + bi], wv, sv[bi]);
                }
            }

            float tot = red32(acc, lane);     // lane L: j = L>>3, bi = L&7
            const int j  = lane >> 3;
            const int bi = lane & 7;
            const int b  = b0 + bi;
            const int n  = nc0 + j;
            float c  = tanhf(tot + sBc[j]);
            float u  = __ldcg(g_uq + (size_t)b * ITR + n);
            float hi = __ldcg(hrow(hid, out, t, b) + GST + n);
            float nh = u * hi + (1.0f - u) * c;
            out[((size_t)b * TT + t) * HH + GST + n] = nh;
        }
        sense ^= 1u; grid_barrier(sense);

        // ============ phase 3: ghost = tanh(new_h @ Wh^T + bh) ============
        for (int g = 0; g < 2; ++g) {
            const int b0 = g * 64 + wrp * 8;
            const float4* np[8];
            #pragma unroll
            for (int bi = 0; bi < 8; ++bi) {
                const int b = b0 + bi;
                np[bi] = (const float4*)(out + ((size_t)b * TT + t) * HH + GST);
            }

            float acc[32];
            #pragma unroll
            for (int i = 0; i < 32; ++i) acc[i] = 0.f;

            #pragma unroll
            for (int kc = 0; kc < 4; ++kc) {           // new_h: 128 float4
                const int k4 = kc * 32 + lane;
                float4 sv[8];
                #pragma unroll
                for (int bi = 0; bi < 8; ++bi) sv[bi] = __ldcg(np[bi] + k4);
                #pragma unroll
                for (int j = 0; j < RH; ++j) {
                    float4 wv = sWh4[j * 128 + k4];
                    #pragma unroll
                    for (int bi = 0; bi < 8; ++bi) fma4(acc[j * 8 + bi], wv, sv[bi]);
                }
            }

            float tot = red32(acc, lane);
            const int j  = lane >> 3;
            const int bi = lane & 7;
            const int b  = b0 + bi;
            const int n  = nh0 + j;
            float gh = tanhf(tot + sBh[j]);
            out[((size_t)b * TT + t) * HH + n] = gh;
        }
        sense ^= 1u; grid_barrier(sense);
        // 3 * 512 = 1536 barriers total (even) -> sense/flag end at 0: replay-safe.
    }

    // ---- h_final tail: copy out row (T-1) into (B, 1, H) region ----
    if (out_size >= (int)((size_t)BB * TT * HH + (size_t)BB * HH)) {
        float* hf = out + (size_t)BB * TT * HH;
        const int total = BB * HH;
        for (int i = cta * NTHR + tid; i < total; i += NCTAS * NTHR) {
            const int b = i / HH;
            const int c = i % HH;
            hf[i] = __ldcg(out + ((size_t)b * TT + (TT - 1)) * HH + c);
        }
    }
}

extern "C" void kernel_launch(void* const* d_in, const int* in_sizes, int n_in,
                              void* d_out, int out_size) {
    const float* x   = (const float*)d_in[0];
    const float* hid = (const float*)d_in[1];
    const float* Wg  = (const float*)d_in[2];
    const float* Wc  = (const float*)d_in[3];
    const float* Wh  = (const float*)d_in[4];
    const float* bg  = (const float*)d_in[5];
    const float* bc  = (const float*)d_in[6];
    const float* bh  = (const float*)d_in[7];
    float* out = (float*)d_out;

    const int smem_bytes = (RG * KGC + RC * KGC + RH * ITR + RG + RC + RH)
                           * (int)sizeof(float);   // 69,696 B
    cudaFuncSetAttribute(ghostgru_persistent,
                         cudaFuncAttributeMaxDynamicSharedMemorySize, smem_bytes);

    ghostgru_persistent<<<NCTAS, NTHR, smem_bytes>>>(
        x, hid, Wg, Wc, Wh, bg, bc, bh, out, out_size);
}

// round 6
// speedup vs baseline: 1.0232x; 1.0232x over previous
#include <cuda_runtime.h>
#include <math.h>

// Problem constants
#define BB     128
#define TT     512
#define FF     256
#define HH     1024
#define GST    512
#define ITR    512
#define KGC    1280
#define NP     64       // batch pairs (BB/2)

// Launch shape
#define NCTAS  128
#define NTHR   256
#define RG     8        // gate rows per CTA   (1024 / 128)
#define RC     4        // cand rows per CTA   (512 / 128)
#define RH     4        // ghost rows per CTA  (512 / 128)

typedef unsigned long long ull;

// ---------------- device globals (scratch + barrier state) ----------------
__device__ unsigned g_bar_count = 0;
__device__ unsigned g_bar_sense = 0;
// packed x: [t][pair][k][2]  (512*64*512 floats = 67 MB)
__device__ __align__(16) float g_xp[(size_t)TT * NP * 2 * FF];
// packed hidden state ping-pong: [buf][pair][k][2]
__device__ __align__(16) float g_hp[2][NP * 2 * HH];
// packed r*h and u: [pair][n][2]
__device__ __align__(16) float g_rp[NP * 2 * ITR];
__device__ __align__(16) float g_up[NP * 2 * ITR];

// Grid-wide sense-reversing barrier (128 CTAs <= 148 SMs, 1 CTA/SM: one wave).
__device__ __forceinline__ void grid_barrier(unsigned sense) {
    __syncthreads();
    if (threadIdx.x == 0) {
        __threadfence();
        unsigned old = atomicInc(&g_bar_count, NCTAS - 1u);
        if (old == NCTAS - 1u) {
            atomicExch(&g_bar_sense, sense);
        } else {
            while (((volatile unsigned*)&g_bar_sense)[0] != sense) { }
        }
        __threadfence();
    }
    __syncthreads();
}

// ---------------- f32x2 packed-math helpers ----------------
__device__ __forceinline__ void ffma2(ull& acc, ull w, ull s) {
    asm("fma.rn.f32x2 %0, %1, %2, %0;" : "+l"(acc) : "l"(w), "l"(s));
}
__device__ __forceinline__ ull addf2(ull a, ull b) {
    ull r; asm("add.rn.f32x2 %0, %1, %2;" : "=l"(r) : "l"(a), "l"(b)); return r;
}
__device__ __forceinline__ ull splat2(float v) {
    ull r; asm("mov.b64 %0, {%1, %1};" : "=l"(r) : "r"(__float_as_uint(v))); return r;
}
__device__ __forceinline__ float f2lo(ull v) { return __uint_as_float((unsigned)v); }
__device__ __forceinline__ float f2hi(ull v) { return __uint_as_float((unsigned)(v >> 32)); }

// Multi-value butterfly reduction over 32 packed accs:
// lane L ends holding the cross-lane total of v[L] (an f32x2 pair).
__device__ __forceinline__ ull red32u(ull* v, int lane) {
    #pragma unroll
    for (int i = 0; i < 16; ++i) {
        ull a = addf2(v[i],      __shfl_xor_sync(0xffffffffu, v[i],      16));
        ull b = addf2(v[i + 16], __shfl_xor_sync(0xffffffffu, v[i + 16], 16));
        v[i] = (lane & 16) ? b : a;
    }
    #pragma unroll
    for (int i = 0; i < 8; ++i) {
        ull a = addf2(v[i],     __shfl_xor_sync(0xffffffffu, v[i],     8));
        ull b = addf2(v[i + 8], __shfl_xor_sync(0xffffffffu, v[i + 8], 8));
        v[i] = (lane & 8) ? b : a;
    }
    #pragma unroll
    for (int i = 0; i < 4; ++i) {
        ull a = addf2(v[i],     __shfl_xor_sync(0xffffffffu, v[i],     4));
        ull b = addf2(v[i + 4], __shfl_xor_sync(0xffffffffu, v[i + 4], 4));
        v[i] = (lane & 4) ? b : a;
    }
    #pragma unroll
    for (int i = 0; i < 2; ++i) {
        ull a = addf2(v[i],     __shfl_xor_sync(0xffffffffu, v[i],     2));
        ull b = addf2(v[i + 2], __shfl_xor_sync(0xffffffffu, v[i + 2], 2));
        v[i] = (lane & 2) ? b : a;
    }
    {
        ull a = addf2(v[0], __shfl_xor_sync(0xffffffffu, v[0], 1));
        ull b = addf2(v[1], __shfl_xor_sync(0xffffffffu, v[1], 1));
        v[0] = (lane & 1) ? b : a;
    }
    return v[0];
}

// ---------------- pre-pass: pack x and h0 into pair-interleaved layout ----------------
extern "C" __global__ void ghostgru_pack(const float* __restrict__ x,
                                         const float* __restrict__ hid) {
    const size_t nx = (size_t)TT * NP * 2 * FF;      // 16.78M
    for (size_t i = (size_t)blockIdx.x * blockDim.x + threadIdx.x; i < nx;
         i += (size_t)gridDim.x * blockDim.x) {
        unsigned h = (unsigned)(i & 1);
        unsigned k = (unsigned)((i >> 1) & (FF - 1));
        unsigned p = (unsigned)((i >> 9) & (NP - 1));
        unsigned t = (unsigned)(i >> 15);
        g_xp[i] = x[((size_t)(2u * p + h) * TT + t) * FF + k];
    }
    const int nh = NP * 2 * HH;                      // 131072
    for (int i = blockIdx.x * blockDim.x + threadIdx.x; i < nh;
         i += gridDim.x * blockDim.x) {
        int h = i & 1;
        int k = (i >> 1) & (HH - 1);
        int p = i >> 11;
        g_hp[0][i] = hid[(2 * p + h) * HH + k];
    }
}

// ---------------- persistent weight-stationary kernel ----------------
extern "C" __global__ void __launch_bounds__(NTHR, 1)
ghostgru_persistent(const float* __restrict__ Wg,    // (1024, 1280)
                    const float* __restrict__ Wc,    // (512, 1280)
                    const float* __restrict__ Wh,    // (512, 512)
                    const float* __restrict__ bg,
                    const float* __restrict__ bc,
                    const float* __restrict__ bh,
                    float*       __restrict__ out,   // (B,T,H) [+ (B,H) tail]
                    int out_size)
{
    extern __shared__ float sm[];
    float* sWg = sm;                        // RG*KGC*2 = 20480 floats (dup pairs)
    float* sWc = sWg + RG * KGC * 2;        // RC*KGC*2 = 10240
    float* sWh = sWc + RC * KGC * 2;        // RH*ITR*2 = 4096
    float* sBg = sWh + RH * ITR * 2;        // RG
    float* sBc = sBg + RG;                  // RC
    float* sBh = sBc + RC;                  // RH

    const int cta  = blockIdx.x;
    const int tid  = threadIdx.x;
    const int wrp  = tid >> 5;
    const int lane = tid & 31;

    // Stage weights duplicated: each scalar w stored as adjacent (w, w).
    for (int i = tid; i < RG * KGC; i += NTHR) {
        float w = Wg[(size_t)cta * (RG * KGC) + i];
        ((float2*)sWg)[i] = make_float2(w, w);
    }
    for (int i = tid; i < RC * KGC; i += NTHR) {
        float w = Wc[(size_t)cta * (RC * KGC) + i];
        ((float2*)sWc)[i] = make_float2(w, w);
    }
    for (int i = tid; i < RH * ITR; i += NTHR) {
        float w = Wh[(size_t)cta * (RH * ITR) + i];
        ((float2*)sWh)[i] = make_float2(w, w);
    }
    if (tid < RG) sBg[tid] = bg[cta * RG + tid];
    if (tid < RC) sBc[tid] = bc[cta * RC + tid];
    if (tid < RH) sBh[tid] = bh[cta * RH + tid];
    __syncthreads();

    const ulonglong2* sWgU = (const ulonglong2*)sWg;   // 640 u2 per row
    const ulonglong2* sWcU = (const ulonglong2*)sWc;   // 640 u2 per row
    const ulonglong2* sWhU = (const ulonglong2*)sWh;   // 256 u2 per row

    const int  ng0  = cta * RG;
    const int  nc0  = cta * RC;
    const int  nh0  = cta * RH;
    const bool is_r = (ng0 < ITR);          // CTAs 0..63 own r rows, 64..127 own u

    unsigned sense = 0;

    for (int t = 0; t < TT; ++t) {
        const float* hpc = g_hp[t & 1];
        float*       hpn = g_hp[(t + 1) & 1];
        const float* xrow = g_xp + (size_t)t * (NP * 2 * FF);

        // ======= phase 1: gate = sigmoid([x_t, h] @ Wg^T + bg) =======
        // warp: 8 neurons x 4 pairs (8 batches), 2 groups.
        #pragma unroll 1
        for (int g = 0; g < 2; ++g) {
            const int p0 = g * 32 + wrp * 4;
            const ulonglong2* xP0 = (const ulonglong2*)(xrow + (size_t)(p0 + 0) * 512);
            const ulonglong2* xP1 = (const ulonglong2*)(xrow + (size_t)(p0 + 1) * 512);
            const ulonglong2* xP2 = (const ulonglong2*)(xrow + (size_t)(p0 + 2) * 512);
            const ulonglong2* xP3 = (const ulonglong2*)(xrow + (size_t)(p0 + 3) * 512);
            const ulonglong2* hP0 = (const ulonglong2*)(hpc + (size_t)(p0 + 0) * 2048);
            const ulonglong2* hP1 = (const ulonglong2*)(hpc + (size_t)(p0 + 1) * 2048);
            const ulonglong2* hP2 = (const ulonglong2*)(hpc + (size_t)(p0 + 2) * 2048);
            const ulonglong2* hP3 = (const ulonglong2*)(hpc + (size_t)(p0 + 3) * 2048);

            ull acc[32];
            #pragma unroll
            for (int i = 0; i < 32; ++i) acc[i] = 0ull;

            #pragma unroll
            for (int it = 0; it < 4; ++it) {            // x segment: u2 [0,128)
                const int off = it * 32 + lane;
                ulonglong2 s0 = __ldcg(xP0 + off);
                ulonglong2 s1 = __ldcg(xP1 + off);
                ulonglong2 s2 = __ldcg(xP2 + off);
                ulonglong2 s3 = __ldcg(xP3 + off);
                #pragma unroll
                for (int j = 0; j < RG; ++j) {
                    ulonglong2 wv = sWgU[j * 640 + off];
                    ffma2(acc[j * 4 + 0], wv.x, s0.x); ffma2(acc[j * 4 + 0], wv.y, s0.y);
                    ffma2(acc[j * 4 + 1], wv.x, s1.x); ffma2(acc[j * 4 + 1], wv.y, s1.y);
                    ffma2(acc[j * 4 + 2], wv.x, s2.x); ffma2(acc[j * 4 + 2], wv.y, s2.y);
                    ffma2(acc[j * 4 + 3], wv.x, s3.x); ffma2(acc[j * 4 + 3], wv.y, s3.y);
                }
            }
            #pragma unroll 4
            for (int it = 0; it < 16; ++it) {           // h segment: u2 [0,512)
                const int off = it * 32 + lane;
                ulonglong2 s0 = __ldcg(hP0 + off);
                ulonglong2 s1 = __ldcg(hP1 + off);
                ulonglong2 s2 = __ldcg(hP2 + off);
                ulonglong2 s3 = __ldcg(hP3 + off);
                #pragma unroll
                for (int j = 0; j < RG; ++j) {
                    ulonglong2 wv = sWgU[j * 640 + 128 + off];
                    ffma2(acc[j * 4 + 0], wv.x, s0.x); ffma2(acc[j * 4 + 0], wv.y, s0.y);
                    ffma2(acc[j * 4 + 1], wv.x, s1.x); ffma2(acc[j * 4 + 1], wv.y, s1.y);
                    ffma2(acc[j * 4 + 2], wv.x, s2.x); ffma2(acc[j * 4 + 2], wv.y, s2.y);
                    ffma2(acc[j * 4 + 3], wv.x, s3.x); ffma2(acc[j * 4 + 3], wv.y, s3.y);
                }
            }

            ull tot = red32u(acc, lane);      // lane L: j = L>>2, pp = L&3
            const int j  = lane >> 2;
            const int pp = lane & 3;
            const int p  = p0 + pp;
            const int n  = ng0 + j;
            ull zb = addf2(tot, splat2(sBg[j]));
            float z0 = f2lo(zb), z1 = f2hi(zb);
            float g0 = 1.0f / (1.0f + __expf(-z0));
            float g1 = 1.0f / (1.0f + __expf(-z1));
            if (is_r) {
                float2 hv = __ldcg((const float2*)(hpc + (size_t)p * 2048 + (GST + n) * 2));
                *(float2*)(g_rp + (size_t)p * 1024 + n * 2) = make_float2(g0 * hv.x, g1 * hv.y);
            } else {
                *(float2*)(g_up + (size_t)p * 1024 + (n - GST) * 2) = make_float2(g0, g1);
            }
        }
        sense ^= 1u; grid_barrier(sense);

        // ======= phase 2: c = tanh([x, h_ghost, r_state] @ Wc^T + bc); new_h =======
        // warp: 4 neurons x 8 pairs (16 batches), single group.
        {
            const int p0 = wrp * 8;
            ull acc[32];
            #pragma unroll
            for (int i = 0; i < 32; ++i) acc[i] = 0ull;

            #pragma unroll
            for (int it = 0; it < 4; ++it) {            // x segment
                const int off = it * 32 + lane;
                ulonglong2 sv[8];
                #pragma unroll
                for (int pp = 0; pp < 8; ++pp)
                    sv[pp] = __ldcg((const ulonglong2*)(xrow + (size_t)(p0 + pp) * 512) + off);
                #pragma unroll
                for (int j = 0; j < RC; ++j) {
                    ulonglong2 wv = sWcU[j * 640 + off];
                    #pragma unroll
                    for (int pp = 0; pp < 8; ++pp) {
                        ffma2(acc[j * 8 + pp], wv.x, sv[pp].x);
                        ffma2(acc[j * 8 + pp], wv.y, sv[pp].y);
                    }
                }
            }
            #pragma unroll 4
            for (int it = 0; it < 8; ++it) {            // h ghost part: u2 [0,256)
                const int off = it * 32 + lane;
                ulonglong2 sv[8];
                #pragma unroll
                for (int pp = 0; pp < 8; ++pp)
                    sv[pp] = __ldcg((const ulonglong2*)(hpc + (size_t)(p0 + pp) * 2048) + off);
                #pragma unroll
                for (int j = 0; j < RC; ++j) {
                    ulonglong2 wv = sWcU[j * 640 + 128 + off];
                    #pragma unroll
                    for (int pp = 0; pp < 8; ++pp) {
                        ffma2(acc[j * 8 + pp], wv.x, sv[pp].x);
                        ffma2(acc[j * 8 + pp], wv.y, sv[pp].y);
                    }
                }
            }
            #pragma unroll 4
            for (int it = 0; it < 8; ++it) {            // r_state: u2 [0,256)
                const int off = it * 32 + lane;
                ulonglong2 sv[8];
                #pragma unroll
                for (int pp = 0; pp < 8; ++pp)
                    sv[pp] = __ldcg((const ulonglong2*)(g_rp + (size_t)(p0 + pp) * 1024) + off);
                #pragma unroll
                for (int j = 0; j < RC; ++j) {
                    ulonglong2 wv = sWcU[j * 640 + 384 + off];
                    #pragma unroll
                    for (int pp = 0; pp < 8; ++pp) {
                        ffma2(acc[j * 8 + pp], wv.x, sv[pp].x);
                        ffma2(acc[j * 8 + pp], wv.y, sv[pp].y);
                    }
                }
            }

            ull tot = red32u(acc, lane);      // lane L: j = L>>3, pp = L&7
            const int j  = lane >> 3;
            const int pp = lane & 7;
            const int p  = p0 + pp;
            const int n  = nc0 + j;
            ull zb = addf2(tot, splat2(sBc[j]));
            float c0 = tanhf(f2lo(zb));
            float c1 = tanhf(f2hi(zb));
            float2 uv = __ldcg((const float2*)(g_up + (size_t)p * 1024 + n * 2));
            float2 hv = __ldcg((const float2*)(hpc + (size_t)p * 2048 + (GST + n) * 2));
            float nh0v = uv.x * hv.x + (1.0f - uv.x) * c0;
            float nh1v = uv.y * hv.y + (1.0f - uv.y) * c1;
            out[((size_t)(2 * p + 0) * TT + t) * HH + GST + n] = nh0v;
            out[((size_t)(2 * p + 1) * TT + t) * HH + GST + n] = nh1v;
            *(float2*)(hpn + (size_t)p * 2048 + (GST + n) * 2) = make_float2(nh0v, nh1v);
        }
        sense ^= 1u; grid_barrier(sense);

        // ======= phase 3: ghost = tanh(new_h @ Wh^T + bh) =======
        {
            const int p0 = wrp * 8;
            ull acc[32];
            #pragma unroll
            for (int i = 0; i < 32; ++i) acc[i] = 0ull;

            #pragma unroll 4
            for (int it = 0; it < 8; ++it) {            // new_h (intr part of hpn)
                const int off = it * 32 + lane;
                ulonglong2 sv[8];
                #pragma unroll
                for (int pp = 0; pp < 8; ++pp)
                    sv[pp] = __ldcg((const ulonglong2*)(hpn + (size_t)(p0 + pp) * 2048)
                                    + 256 + off);
                #pragma unroll
                for (int j = 0; j < RH; ++j) {
                    ulonglong2 wv = sWhU[j * 256 + off];
                    #pragma unroll
                    for (int pp = 0; pp < 8; ++pp) {
                        ffma2(acc[j * 8 + pp], wv.x, sv[pp].x);
                        ffma2(acc[j * 8 + pp], wv.y, sv[pp].y);
                    }
                }
            }

            ull tot = red32u(acc, lane);
            const int j  = lane >> 3;
            const int pp = lane & 7;
            const int p  = p0 + pp;
            const int n  = nh0 + j;
            ull zb = addf2(tot, splat2(sBh[j]));
            float gh0 = tanhf(f2lo(zb));
            float gh1 = tanhf(f2hi(zb));
            out[((size_t)(2 * p + 0) * TT + t) * HH + n] = gh0;
            out[((size_t)(2 * p + 1) * TT + t) * HH + n] = gh1;
            *(float2*)(hpn + (size_t)p * 2048 + n * 2) = make_float2(gh0, gh1);
        }
        sense ^= 1u; grid_barrier(sense);
        // 3 * 512 = 1536 barriers (even): sense/flag end at 0 -> replay-safe.
    }

    // ---- h_final tail: copy out row (T-1) into the (B, 1, H) region ----
    if (out_size >= (int)((size_t)BB * TT * HH + (size_t)BB * HH)) {
        float* hf = out + (size_t)BB * TT * HH;
        const int total = BB * HH;
        for (int i = cta * NTHR + tid; i < total; i += NCTAS * NTHR) {
            const int b = i / HH;
            const int c = i % HH;
            hf[i] = __ldcg(out + ((size_t)b * TT + (TT - 1)) * HH + c);
        }
    }
}

extern "C" void kernel_launch(void* const* d_in, const int* in_sizes, int n_in,
                              void* d_out, int out_size) {
    const float* x   = (const float*)d_in[0];
    const float* hid = (const float*)d_in[1];
    const float* Wg  = (const float*)d_in[2];
    const float* Wc  = (const float*)d_in[3];
    const float* Wh  = (const float*)d_in[4];
    const float* bg  = (const float*)d_in[5];
    const float* bc  = (const float*)d_in[6];
    const float* bh  = (const float*)d_in[7];
    float* out = (float*)d_out;

    ghostgru_pack<<<2048, 256>>>(x, hid);

    const int smem_bytes = (RG * KGC * 2 + RC * KGC * 2 + RH * ITR * 2
                            + RG + RC + RH) * (int)sizeof(float);   // 139,328 B
    cudaFuncSetAttribute(ghostgru_persistent,
                         cudaFuncAttributeMaxDynamicSharedMemorySize, smem_bytes);

    ghostgru_persistent<<<NCTAS, NTHR, smem_bytes>>>(
        Wg, Wc, Wh, bg, bc, bh, out, out_size);
}